// round 11
// baseline (speedup 1.0000x reference)
#include <cuda_runtime.h>
#include <cuda_fp16.h>

// Problem dims (fixed): B=8, N=1024, C=256, H=4, D=64
#define Bb   8
#define Nn   1024
#define Cc   256
#define Hh   4
#define Dd   64
#define HD   256               // H*D
#define ROWS (Bb * Nn)         // 8192
#define NEG_SLOPE 0.2f

// Scratch (device globals: allocation-free rule)
__device__ __half g_Wxh[ROWS * HD]; // 4 MB  (fp16 Wx — only consumer is the gather)
__device__ float  g_ei[ROWS * Hh];
__device__ float  g_ej[ROWS * Hh];

// ---------------------------------------------------------------------------
// Kernel 1: Wx = x @ W  (8192x256 @ 256x256), 128x64 tiles, 8x4 per thread,
// double-buffered smem (1 sync per k-tile), fp16 Wx store,
// fused e_i/e_j epilogue (1 head per col-tile).   (unchanged from 66.0us run)
// ---------------------------------------------------------------------------
__global__ void __launch_bounds__(256) gemm_fused_k(const float* __restrict__ A,
                                                    const float* __restrict__ Bm,
                                                    const float* __restrict__ avec) {
    __shared__ float As[2][16][132];     // k-major, padded
    __shared__ float Bs[2][16][68];
    __shared__ float s_ai[64], s_aj[64];

    const int tid = threadIdx.x;
    const int tx = tid & 15;          // 0..15 -> 4 cols each
    const int ty = tid >> 4;          // 0..15 -> 8 rows each
    const int row0 = blockIdx.x * 128;
    const int col0 = blockIdx.y * 64;
    const int h = blockIdx.y;         // head index

    if (tid < 64) {
        s_ai[tid] = avec[h * 128 + tid];
        s_aj[tid] = avec[h * 128 + 64 + tid];
    }

    float acc[8][4] = {};

    const int ar = tid >> 1;
    const int ac = (tid & 1) * 8;
    const int br = tid >> 4;
    const int bc = (tid & 15) * 4;

    const float* aptr = &A[(size_t)(row0 + ar) * Cc + ac];
    const float* bptr = &Bm[(size_t)br * HD + col0 + bc];

    // load tile 0 into buffer 0
    float4 a0 = *(const float4*)(aptr);
    float4 a1 = *(const float4*)(aptr + 4);
    float4 bv = *(const float4*)(bptr);
    As[0][ac + 0][ar] = a0.x; As[0][ac + 1][ar] = a0.y;
    As[0][ac + 2][ar] = a0.z; As[0][ac + 3][ar] = a0.w;
    As[0][ac + 4][ar] = a1.x; As[0][ac + 5][ar] = a1.y;
    As[0][ac + 6][ar] = a1.z; As[0][ac + 7][ar] = a1.w;
    *(float4*)&Bs[0][br][bc] = bv;
    __syncthreads();

#pragma unroll
    for (int t = 0; t < 16; t++) {
        const int cur = t & 1;
        const int nxt = cur ^ 1;
        if (t < 15) {   // prefetch next tile
            const int k0 = (t + 1) * 16;
            a0 = *(const float4*)(aptr + k0);
            a1 = *(const float4*)(aptr + k0 + 4);
            bv = *(const float4*)(bptr + (size_t)k0 * HD);
        }

#pragma unroll
        for (int kk = 0; kk < 16; kk++) {
            float4 av0 = *(float4*)&As[cur][kk][ty * 8];
            float4 av1 = *(float4*)&As[cur][kk][ty * 8 + 4];
            float4 bv4 = *(float4*)&Bs[cur][kk][tx * 4];
            float aa[8] = { av0.x, av0.y, av0.z, av0.w, av1.x, av1.y, av1.z, av1.w };
            float bb[4] = { bv4.x, bv4.y, bv4.z, bv4.w };
#pragma unroll
            for (int i = 0; i < 8; i++)
#pragma unroll
                for (int j = 0; j < 4; j++)
                    acc[i][j] = fmaf(aa[i], bb[j], acc[i][j]);
        }

        if (t < 15) {
            As[nxt][ac + 0][ar] = a0.x; As[nxt][ac + 1][ar] = a0.y;
            As[nxt][ac + 2][ar] = a0.z; As[nxt][ac + 3][ar] = a0.w;
            As[nxt][ac + 4][ar] = a1.x; As[nxt][ac + 5][ar] = a1.y;
            As[nxt][ac + 6][ar] = a1.z; As[nxt][ac + 7][ar] = a1.w;
            *(float4*)&Bs[nxt][br][bc] = bv;
        }
        __syncthreads();
    }

    // Store Wx as fp16
#pragma unroll
    for (int i = 0; i < 8; i++) {
        __half2 h01 = __floats2half2_rn(acc[i][0], acc[i][1]);
        __half2 h23 = __floats2half2_rn(acc[i][2], acc[i][3]);
        uint2 u;
        u.x = *(unsigned int*)&h01;
        u.y = *(unsigned int*)&h23;
        *(uint2*)&g_Wxh[(size_t)(row0 + ty * 8 + i) * HD + col0 + tx * 4] = u;
    }

    // Fused e_i / e_j epilogue (fp32 accumulators)
    float pi[8], pj[8];
#pragma unroll
    for (int i = 0; i < 8; i++) {
        float si = 0.0f, sj = 0.0f;
#pragma unroll
        for (int j = 0; j < 4; j++) {
            si = fmaf(acc[i][j], s_ai[tx * 4 + j], si);
            sj = fmaf(acc[i][j], s_aj[tx * 4 + j], sj);
        }
        pi[i] = si; pj[i] = sj;
    }
#pragma unroll
    for (int off = 8; off > 0; off >>= 1) {
#pragma unroll
        for (int i = 0; i < 8; i++) {
            pi[i] += __shfl_down_sync(0xffffffffu, pi[i], off, 16);
            pj[i] += __shfl_down_sync(0xffffffffu, pj[i], off, 16);
        }
    }
    if (tx == 0) {
#pragma unroll
        for (int i = 0; i < 8; i++) {
            int row = row0 + ty * 8 + i;
            g_ei[row * Hh + h] = pi[i];
            g_ej[row * Hh + h] = pj[i];
        }
    }
}

// ---------------------------------------------------------------------------
// Kernel 2: sparse masked softmax + fp16 gather. 1 block per (b,n).
// Gather: 8 outputs/thread via LDG.128 (uint4 = 8 halves); 8 warp-groups
// strided over k. s_idx holds j*32 (uint4-row offsets).
// ---------------------------------------------------------------------------
__global__ void __launch_bounds__(256) attn_k(const float* __restrict__ adj,
                                              float* __restrict__ out) {
    __shared__ int   s_idx[Nn];          // compacted j*32 offsets (ordered)
    __shared__ float s_w[Nn * Hh];       // [k][h] exp-weights (float4 per k)
    __shared__ int   s_tot[8];
    __shared__ float s_rsum[8][4];
    __shared__ float s_acc[8][HD];       // [grp][256] partial accumulators (8KB)

    const int tid  = threadIdx.x;
    const int blk  = blockIdx.x;          // b*N + n
    const int b    = blk >> 10;
    const int n    = blk & 1023;
    const int warp = tid >> 5;
    const int lane = tid & 31;

    // ---- compaction: each thread owns 4 consecutive j ----
    const float4* arow4 = (const float4*)(adj + (size_t)blk * Nn);
    float4 v = arow4[tid];
    const int j0 = tid * 4;
    unsigned mk = 0;
    if (v.x != 0.0f || j0     == n) mk |= 1u;
    if (v.y != 0.0f || j0 + 1 == n) mk |= 2u;
    if (v.z != 0.0f || j0 + 2 == n) mk |= 4u;
    if (v.w != 0.0f || j0 + 3 == n) mk |= 8u;
    int cnt = __popc(mk);
    int scan = cnt;
#pragma unroll
    for (int off = 1; off < 32; off <<= 1) {
        int t = __shfl_up_sync(0xffffffffu, scan, off);
        if (lane >= off) scan += t;
    }
    if (lane == 31) s_tot[warp] = scan;
    __syncthreads();
    int base = 0, K = 0;
#pragma unroll
    for (int w = 0; w < 8; w++) {
        int t = s_tot[w];
        if (w < warp) base += t;
        K += t;
    }
    int pos0 = base + (scan - cnt);
    if (mk & 1u) s_idx[pos0++] = (j0    ) * 32;   // row offset in uint4 units
    if (mk & 2u) s_idx[pos0++] = (j0 + 1) * 32;
    if (mk & 4u) s_idx[pos0++] = (j0 + 2) * 32;
    if (mk & 8u) s_idx[pos0++] = (j0 + 3) * 32;
    __syncthreads();

    // ---- fused score + exp + sum (no max-subtract: scores bounded, fp32-safe) ----
    float4 eiv = *(const float4*)&g_ei[blk * Hh];
    const float4* ej4 = (const float4*)g_ej;
    float lsum[4] = {};
    for (int k = tid; k < K; k += 256) {
        int j = s_idx[k] >> 5;
        float4 ejv = __ldg(&ej4[(b << 10) + j]);
        float s0 = eiv.x + ejv.x, s1 = eiv.y + ejv.y;
        float s2 = eiv.z + ejv.z, s3 = eiv.w + ejv.w;
        s0 = s0 > 0.0f ? s0 : NEG_SLOPE * s0;
        s1 = s1 > 0.0f ? s1 : NEG_SLOPE * s1;
        s2 = s2 > 0.0f ? s2 : NEG_SLOPE * s2;
        s3 = s3 > 0.0f ? s3 : NEG_SLOPE * s3;
        float w0 = __expf(s0), w1 = __expf(s1);
        float w2 = __expf(s2), w3 = __expf(s3);
        *(float4*)&s_w[k * Hh] = make_float4(w0, w1, w2, w3);
        lsum[0] += w0; lsum[1] += w1; lsum[2] += w2; lsum[3] += w3;
    }
#pragma unroll
    for (int off = 16; off > 0; off >>= 1)
#pragma unroll
        for (int h = 0; h < 4; h++)
            lsum[h] += __shfl_xor_sync(0xffffffffu, lsum[h], off);
    if (lane == 0)
#pragma unroll
        for (int h = 0; h < 4; h++) s_rsum[warp][h] = lsum[h];
    __syncthreads();   // orders s_w / s_idx writes before gather reads

    // ---- fp16 gather: 8 outputs/thread. pos = lane (32 pos x 8 halves = 256),
    //      grp = warp; each warp takes k = grp, grp+8, ... ----
    const int pos = lane;                // uint4 column 0..31
    const int grp = warp;
    const int hh  = pos >> 3;            // head of this 8-float chunk
    const uint4* hw = (const uint4*)(g_Wxh + (size_t)b * (Nn * HD));
    float a0 = 0.f, a1 = 0.f, a2 = 0.f, a3 = 0.f;
    float a4 = 0.f, a5 = 0.f, a6 = 0.f, a7 = 0.f;
    int k = grp;
    for (; k + 8 < K; k += 16) {
        int   oa = s_idx[k] + pos,      ob = s_idx[k + 8] + pos;
        float wa = s_w[k * Hh + hh],    wb = s_w[(k + 8) * Hh + hh];
        uint4 ua = __ldg(&hw[oa]);
        uint4 ub = __ldg(&hw[ob]);
        float2 p0 = __half22float2(*(__half2*)&ua.x);
        float2 p1 = __half22float2(*(__half2*)&ua.y);
        float2 p2 = __half22float2(*(__half2*)&ua.z);
        float2 p3 = __half22float2(*(__half2*)&ua.w);
        a0 = fmaf(wa, p0.x, a0); a1 = fmaf(wa, p0.y, a1);
        a2 = fmaf(wa, p1.x, a2); a3 = fmaf(wa, p1.y, a3);
        a4 = fmaf(wa, p2.x, a4); a5 = fmaf(wa, p2.y, a5);
        a6 = fmaf(wa, p3.x, a6); a7 = fmaf(wa, p3.y, a7);
        float2 q0 = __half22float2(*(__half2*)&ub.x);
        float2 q1 = __half22float2(*(__half2*)&ub.y);
        float2 q2 = __half22float2(*(__half2*)&ub.z);
        float2 q3 = __half22float2(*(__half2*)&ub.w);
        a0 = fmaf(wb, q0.x, a0); a1 = fmaf(wb, q0.y, a1);
        a2 = fmaf(wb, q1.x, a2); a3 = fmaf(wb, q1.y, a3);
        a4 = fmaf(wb, q2.x, a4); a5 = fmaf(wb, q2.y, a5);
        a6 = fmaf(wb, q3.x, a6); a7 = fmaf(wb, q3.y, a7);
    }
    for (; k < K; k += 8) {
        int   o = s_idx[k] + pos;
        float w = s_w[k * Hh + hh];
        uint4 u = __ldg(&hw[o]);
        float2 p0 = __half22float2(*(__half2*)&u.x);
        float2 p1 = __half22float2(*(__half2*)&u.y);
        float2 p2 = __half22float2(*(__half2*)&u.z);
        float2 p3 = __half22float2(*(__half2*)&u.w);
        a0 = fmaf(w, p0.x, a0); a1 = fmaf(w, p0.y, a1);
        a2 = fmaf(w, p1.x, a2); a3 = fmaf(w, p1.y, a3);
        a4 = fmaf(w, p2.x, a4); a5 = fmaf(w, p2.y, a5);
        a6 = fmaf(w, p3.x, a6); a7 = fmaf(w, p3.y, a7);
    }
    *(float4*)&s_acc[grp][pos * 8]     = make_float4(a0, a1, a2, a3);
    *(float4*)&s_acc[grp][pos * 8 + 4] = make_float4(a4, a5, a6, a7);
    __syncthreads();

    // ---- cross-group reduce + normalize + store ----
    if (tid < 64) {
        const int h = tid >> 4;
        float4 r = *(float4*)&s_acc[0][tid * 4];
#pragma unroll
        for (int g = 1; g < 8; g++) {
            float4 t = *(float4*)&s_acc[g][tid * 4];
            r.x += t.x; r.y += t.y; r.z += t.z; r.w += t.w;
        }
        float tot = 0.0f;
#pragma unroll
        for (int w = 0; w < 8; w++) tot += s_rsum[w][h];
        float inv = 1.0f / tot;
        r.x *= inv; r.y *= inv; r.z *= inv; r.w *= inv;
        *(float4*)&out[(size_t)blk * HD + tid * 4] = r;
    }
}

// ---------------------------------------------------------------------------
extern "C" void kernel_launch(void* const* d_in, const int* in_sizes, int n_in,
                              void* d_out, int out_size) {
    const float *x = nullptr, *adj = nullptr, *W = nullptr, *a = nullptr;
    for (int i = 0; i < n_in; i++) {
        switch (in_sizes[i]) {
            case Bb * Nn * Cc:  x   = (const float*)d_in[i]; break;  // 2097152
            case Bb * Nn * Nn:  adj = (const float*)d_in[i]; break;  // 8388608
            case Cc * HD:       W   = (const float*)d_in[i]; break;  // 65536
            case Hh * 2 * Dd:   a   = (const float*)d_in[i]; break;  // 512
        }
    }
    float* out = (float*)d_out;

    dim3 ggrid(ROWS / 128, HD / 64);    // 64 x 4 = 256 blocks
    gemm_fused_k<<<ggrid, 256>>>(x, W, a);
    attn_k<<<ROWS, 256>>>(adj, out);
}

// round 12
// speedup vs baseline: 1.0818x; 1.0818x over previous
#include <cuda_runtime.h>
#include <cuda_fp16.h>
#include <cstdint>

// Problem dims (fixed): B=8, N=1024, C=256, H=4, D=64
#define Bb   8
#define Nn   1024
#define Cc   256
#define Hh   4
#define Dd   64
#define HD   256               // H*D
#define ROWS (Bb * Nn)         // 8192
#define NEG_SLOPE 0.2f

// Scratch (device globals: allocation-free rule)
__device__ __half g_Wxh[ROWS * HD]; // 4 MB  (fp16 Wx — only consumer is the gather)
__device__ float  g_ei[ROWS * Hh];
__device__ float  g_ej[ROWS * Hh];
__device__ float  g_wa[8][Cc];      // W @ [a_i|a_j] per (head, i/j): v = h*2+ij

__device__ __forceinline__ uint32_t f2tf(float f) {
    uint32_t r;
    asm("cvt.rna.tf32.f32 %0, %1;" : "=r"(r) : "f"(f));
    return r;
}
__device__ __forceinline__ float f2tf_f(float f) { return __uint_as_float(f2tf(f)); }

// ---------------------------------------------------------------------------
// Kernel 0: wa[v][c] = sum_d W[c][h*64+d] * a[h, ij*64 + d],  v = h*2+ij.
// grid = 8 blocks (one per v), 256 threads (one per c). fp32-exact.
// ---------------------------------------------------------------------------
__global__ void __launch_bounds__(256) wa_k(const float* __restrict__ W,
                                            const float* __restrict__ avec) {
    __shared__ float s_a[64];
    const int v = blockIdx.x;          // 0..7
    const int h = v >> 1, ij = v & 1;
    const int tid = threadIdx.x;
    if (tid < 64) s_a[tid] = avec[h * 128 + ij * 64 + tid];
    __syncthreads();

    const float* wrow = W + (size_t)tid * HD + h * 64;
    float s = 0.0f;
#pragma unroll
    for (int d = 0; d < 64; d += 4) {
        float4 w4 = __ldg((const float4*)(wrow + d));
        s += w4.x * s_a[d] + w4.y * s_a[d + 1] + w4.z * s_a[d + 2] + w4.w * s_a[d + 3];
    }
    g_wa[v][tid] = s;
}

// ---------------------------------------------------------------------------
// Kernel 0b: e_i/e_j = x . wa  (fp32-exact). One warp per row, 8 warps/block.
// ---------------------------------------------------------------------------
__global__ void __launch_bounds__(256) eij_k(const float* __restrict__ x) {
    __shared__ float s_wa[8][Cc];      // 8 KB
    const int tid  = threadIdx.x;
    const int warp = tid >> 5;
    const int lane = tid & 31;

#pragma unroll
    for (int v = 0; v < 8; v++) s_wa[v][tid] = g_wa[v][tid];

    const int row = blockIdx.x * 8 + warp;
    const float4* xr = (const float4*)(x + (size_t)row * Cc);
    float4 x0 = __ldg(&xr[lane * 2]);
    float4 x1 = __ldg(&xr[lane * 2 + 1]);
    __syncthreads();

    float e[8];
#pragma unroll
    for (int v = 0; v < 8; v++) {
        const float* wv = &s_wa[v][lane * 8];
        e[v] = x0.x * wv[0] + x0.y * wv[1] + x0.z * wv[2] + x0.w * wv[3]
             + x1.x * wv[4] + x1.y * wv[5] + x1.z * wv[6] + x1.w * wv[7];
    }
#pragma unroll
    for (int off = 16; off > 0; off >>= 1)
#pragma unroll
        for (int v = 0; v < 8; v++)
            e[v] += __shfl_xor_sync(0xffffffffu, e[v], off);

    if (lane == 0) {
        *(float4*)&g_ei[row * Hh] = make_float4(e[0], e[2], e[4], e[6]);
        *(float4*)&g_ej[row * Hh] = make_float4(e[1], e[3], e[5], e[7]);
    }
}

// ---------------------------------------------------------------------------
// Kernel 1: Wx = x @ W via tf32 mma.sync (m16n8k8). 128x64 block tile,
// 8 warps (4m x 2n), warp tile 32x32 (2 mtiles x 4 ntiles). fp16 Wx store.
// ---------------------------------------------------------------------------
__global__ void __launch_bounds__(256) gemm_tf32_k(const float* __restrict__ A,
                                                   const float* __restrict__ Bm) {
    __shared__ float As[128][36];    // 32 k-cols + 4 pad (a-frag conflict-free)
    __shared__ float Bs[32][72];     // 64 n-cols + 8 pad (b-frag conflict-free)

    const int tid  = threadIdx.x;
    const int warp = tid >> 5;
    const int lane = tid & 31;
    const int qr = lane >> 2;         // 0..7
    const int qc = lane & 3;          // 0..3
    const int wm = (warp >> 1) * 32;  // warp m offset
    const int wn = (warp & 1) * 32;   // warp n offset
    const int row0 = blockIdx.x * 128;
    const int col0 = blockIdx.y * 64;

    // global load assignments
    const int a_row = tid >> 1, a_col = (tid & 1) * 16;
    const int b_row = tid >> 3, b_col = (tid & 7) * 8;
    const float* aptr = A + (size_t)(row0 + a_row) * Cc + a_col;
    const float* bptr = Bm + (size_t)b_row * HD + col0 + b_col;

    float acc[2][4][4] = {};

    // preload chunk 0
    float4 ra[4], rb[2];
#pragma unroll
    for (int i = 0; i < 4; i++) ra[i] = __ldg((const float4*)(aptr + i * 4));
    rb[0] = __ldg((const float4*)(bptr));
    rb[1] = __ldg((const float4*)(bptr + 4));

#pragma unroll
    for (int chunk = 0; chunk < 8; chunk++) {
        // stage (convert to tf32 at store time)
#pragma unroll
        for (int i = 0; i < 4; i++) {
            *(float4*)&As[a_row][a_col + i * 4] = make_float4(
                f2tf_f(ra[i].x), f2tf_f(ra[i].y), f2tf_f(ra[i].z), f2tf_f(ra[i].w));
        }
        *(float4*)&Bs[b_row][b_col] = make_float4(
            f2tf_f(rb[0].x), f2tf_f(rb[0].y), f2tf_f(rb[0].z), f2tf_f(rb[0].w));
        *(float4*)&Bs[b_row][b_col + 4] = make_float4(
            f2tf_f(rb[1].x), f2tf_f(rb[1].y), f2tf_f(rb[1].z), f2tf_f(rb[1].w));
        __syncthreads();

        if (chunk < 7) {     // prefetch next chunk
            const int k0 = (chunk + 1) * 32;
#pragma unroll
            for (int i = 0; i < 4; i++)
                ra[i] = __ldg((const float4*)(aptr + k0 + i * 4));
            rb[0] = __ldg((const float4*)(bptr + (size_t)k0 * HD));
            rb[1] = __ldg((const float4*)(bptr + (size_t)k0 * HD + 4));
        }

#pragma unroll
        for (int k8 = 0; k8 < 4; k8++) {
            const int kb = k8 * 8;
            uint32_t af[2][4], bf[4][2];
#pragma unroll
            for (int mt = 0; mt < 2; mt++) {
                const int r = wm + mt * 16 + qr;
                af[mt][0] = __float_as_uint(As[r    ][kb + qc]);
                af[mt][1] = __float_as_uint(As[r + 8][kb + qc]);
                af[mt][2] = __float_as_uint(As[r    ][kb + qc + 4]);
                af[mt][3] = __float_as_uint(As[r + 8][kb + qc + 4]);
            }
#pragma unroll
            for (int nt = 0; nt < 4; nt++) {
                const int c = wn + nt * 8 + qr;
                bf[nt][0] = __float_as_uint(Bs[kb + qc    ][c]);
                bf[nt][1] = __float_as_uint(Bs[kb + qc + 4][c]);
            }
#pragma unroll
            for (int mt = 0; mt < 2; mt++)
#pragma unroll
                for (int nt = 0; nt < 4; nt++) {
                    asm volatile(
                        "mma.sync.aligned.m16n8k8.row.col.f32.tf32.tf32.f32 "
                        "{%0,%1,%2,%3}, {%4,%5,%6,%7}, {%8,%9}, {%0,%1,%2,%3};"
                        : "+f"(acc[mt][nt][0]), "+f"(acc[mt][nt][1]),
                          "+f"(acc[mt][nt][2]), "+f"(acc[mt][nt][3])
                        : "r"(af[mt][0]), "r"(af[mt][1]), "r"(af[mt][2]), "r"(af[mt][3]),
                          "r"(bf[nt][0]), "r"(bf[nt][1]));
                }
        }
        __syncthreads();
    }

    // store Wx as fp16 directly from C fragments
#pragma unroll
    for (int mt = 0; mt < 2; mt++) {
        const int r0 = row0 + wm + mt * 16 + qr;
#pragma unroll
        for (int nt = 0; nt < 4; nt++) {
            const int c = col0 + wn + nt * 8 + qc * 2;
            __half2 h0 = __floats2half2_rn(acc[mt][nt][0], acc[mt][nt][1]);
            __half2 h1 = __floats2half2_rn(acc[mt][nt][2], acc[mt][nt][3]);
            *(__half2*)&g_Wxh[(size_t)r0 * HD + c]       = h0;
            *(__half2*)&g_Wxh[(size_t)(r0 + 8) * HD + c] = h1;
        }
    }
}

// ---------------------------------------------------------------------------
// Kernel 2: sparse masked softmax + fp16 gather (round-9 verbatim, 37.1us).
// ---------------------------------------------------------------------------
__global__ void __launch_bounds__(256) attn_k(const float* __restrict__ adj,
                                              float* __restrict__ out) {
    __shared__ int   s_idx[Nn];          // compacted j*64 offsets (ordered)
    __shared__ float s_w[Nn * Hh];       // [k][h] exp-weights (float4 per k)
    __shared__ int   s_tot[8];
    __shared__ float s_rsum[8][4];
    __shared__ float s_acc[4][Hh * 64];  // [grp][pos*4] partial accumulators

    const int tid  = threadIdx.x;
    const int blk  = blockIdx.x;          // b*N + n
    const int b    = blk >> 10;
    const int n    = blk & 1023;
    const int warp = tid >> 5;
    const int lane = tid & 31;

    // ---- compaction: each thread owns 4 consecutive j ----
    const float4* arow4 = (const float4*)(adj + (size_t)blk * Nn);
    float4 v = arow4[tid];
    const int j0 = tid * 4;
    unsigned mk = 0;
    if (v.x != 0.0f || j0     == n) mk |= 1u;
    if (v.y != 0.0f || j0 + 1 == n) mk |= 2u;
    if (v.z != 0.0f || j0 + 2 == n) mk |= 4u;
    if (v.w != 0.0f || j0 + 3 == n) mk |= 8u;
    int cnt = __popc(mk);
    int scan = cnt;
#pragma unroll
    for (int off = 1; off < 32; off <<= 1) {
        int t = __shfl_up_sync(0xffffffffu, scan, off);
        if (lane >= off) scan += t;
    }
    if (lane == 31) s_tot[warp] = scan;
    __syncthreads();
    int base = 0, K = 0;
#pragma unroll
    for (int w = 0; w < 8; w++) {
        int t = s_tot[w];
        if (w < warp) base += t;
        K += t;
    }
    int pos0 = base + (scan - cnt);
    if (mk & 1u) s_idx[pos0++] = (j0    ) * 64;
    if (mk & 2u) s_idx[pos0++] = (j0 + 1) * 64;
    if (mk & 4u) s_idx[pos0++] = (j0 + 2) * 64;
    if (mk & 8u) s_idx[pos0++] = (j0 + 3) * 64;
    __syncthreads();

    // ---- fused score + exp + sum (no max-subtract: scores bounded, fp32-safe) ----
    float4 eiv = *(const float4*)&g_ei[blk * Hh];
    const float4* ej4 = (const float4*)g_ej;
    float lsum[4] = {};
    for (int k = tid; k < K; k += 256) {
        int j = s_idx[k] >> 6;
        float4 ejv = __ldg(&ej4[(b << 10) + j]);
        float s0 = eiv.x + ejv.x, s1 = eiv.y + ejv.y;
        float s2 = eiv.z + ejv.z, s3 = eiv.w + ejv.w;
        s0 = s0 > 0.0f ? s0 : NEG_SLOPE * s0;
        s1 = s1 > 0.0f ? s1 : NEG_SLOPE * s1;
        s2 = s2 > 0.0f ? s2 : NEG_SLOPE * s2;
        s3 = s3 > 0.0f ? s3 : NEG_SLOPE * s3;
        float w0 = __expf(s0), w1 = __expf(s1);
        float w2 = __expf(s2), w3 = __expf(s3);
        *(float4*)&s_w[k * Hh] = make_float4(w0, w1, w2, w3);
        lsum[0] += w0; lsum[1] += w1; lsum[2] += w2; lsum[3] += w3;
    }
#pragma unroll
    for (int off = 16; off > 0; off >>= 1)
#pragma unroll
        for (int h = 0; h < 4; h++)
            lsum[h] += __shfl_xor_sync(0xffffffffu, lsum[h], off);
    if (lane == 0)
#pragma unroll
        for (int h = 0; h < 4; h++) s_rsum[warp][h] = lsum[h];
    __syncthreads();   // orders s_w / s_idx writes before gather reads

    // ---- fp16 gather: pos owns out floats [4pos,4pos+4), grp splits k ----
    const int pos = tid & 63;
    const int grp = tid >> 6;
    const int hh  = pos >> 4;            // head of this float4
    const uint2* hw = (const uint2*)(g_Wxh + (size_t)b * (Nn * HD));
    float4 acc = make_float4(0.f, 0.f, 0.f, 0.f);
    int k = grp;
    for (; k + 12 < K; k += 16) {
        int oa = s_idx[k] + pos,     ob = s_idx[k + 4]  + pos;
        int oc = s_idx[k + 8] + pos, od = s_idx[k + 12] + pos;
        float wa = s_w[(k     ) * Hh + hh], wb = s_w[(k +  4) * Hh + hh];
        float wc = s_w[(k +  8) * Hh + hh], wd = s_w[(k + 12) * Hh + hh];
        uint2 ua = __ldg(&hw[oa]);
        uint2 ub = __ldg(&hw[ob]);
        uint2 uc = __ldg(&hw[oc]);
        uint2 ud = __ldg(&hw[od]);
        float2 a0 = __half22float2(*(__half2*)&ua.x);
        float2 a1 = __half22float2(*(__half2*)&ua.y);
        float2 b0 = __half22float2(*(__half2*)&ub.x);
        float2 b1 = __half22float2(*(__half2*)&ub.y);
        float2 c0 = __half22float2(*(__half2*)&uc.x);
        float2 c1 = __half22float2(*(__half2*)&uc.y);
        float2 d0 = __half22float2(*(__half2*)&ud.x);
        float2 d1 = __half22float2(*(__half2*)&ud.y);
        acc.x = fmaf(wa, a0.x, acc.x); acc.y = fmaf(wa, a0.y, acc.y);
        acc.z = fmaf(wa, a1.x, acc.z); acc.w = fmaf(wa, a1.y, acc.w);
        acc.x = fmaf(wb, b0.x, acc.x); acc.y = fmaf(wb, b0.y, acc.y);
        acc.z = fmaf(wb, b1.x, acc.z); acc.w = fmaf(wb, b1.y, acc.w);
        acc.x = fmaf(wc, c0.x, acc.x); acc.y = fmaf(wc, c0.y, acc.y);
        acc.z = fmaf(wc, c1.x, acc.z); acc.w = fmaf(wc, c1.y, acc.w);
        acc.x = fmaf(wd, d0.x, acc.x); acc.y = fmaf(wd, d0.y, acc.y);
        acc.z = fmaf(wd, d1.x, acc.z); acc.w = fmaf(wd, d1.y, acc.w);
    }
    for (; k < K; k += 4) {
        int o = s_idx[k] + pos;
        float w = s_w[k * Hh + hh];
        uint2 uu = __ldg(&hw[o]);
        float2 l0 = __half22float2(*(__half2*)&uu.x);
        float2 l1 = __half22float2(*(__half2*)&uu.y);
        acc.x = fmaf(w, l0.x, acc.x); acc.y = fmaf(w, l0.y, acc.y);
        acc.z = fmaf(w, l1.x, acc.z); acc.w = fmaf(w, l1.y, acc.w);
    }
    *(float4*)&s_acc[grp][pos * 4] = acc;
    __syncthreads();

    // ---- cross-group reduce + normalize + store ----
    if (tid < 64) {
        const int h = tid >> 4;
        float4 r = *(float4*)&s_acc[0][tid * 4];
#pragma unroll
        for (int g = 1; g < 4; g++) {
            float4 t = *(float4*)&s_acc[g][tid * 4];
            r.x += t.x; r.y += t.y; r.z += t.z; r.w += t.w;
        }
        float tot = 0.0f;
#pragma unroll
        for (int w = 0; w < 8; w++) tot += s_rsum[w][h];
        float inv = 1.0f / tot;
        r.x *= inv; r.y *= inv; r.z *= inv; r.w *= inv;
        *(float4*)&out[(size_t)blk * HD + tid * 4] = r;
    }
}

// ---------------------------------------------------------------------------
extern "C" void kernel_launch(void* const* d_in, const int* in_sizes, int n_in,
                              void* d_out, int out_size) {
    const float *x = nullptr, *adj = nullptr, *W = nullptr, *a = nullptr;
    for (int i = 0; i < n_in; i++) {
        switch (in_sizes[i]) {
            case Bb * Nn * Cc:  x   = (const float*)d_in[i]; break;  // 2097152
            case Bb * Nn * Nn:  adj = (const float*)d_in[i]; break;  // 8388608
            case Cc * HD:       W   = (const float*)d_in[i]; break;  // 65536
            case Hh * 2 * Dd:   a   = (const float*)d_in[i]; break;  // 512
        }
    }
    float* out = (float*)d_out;

    wa_k<<<8, 256>>>(W, a);                       // fp32-exact W@a
    eij_k<<<ROWS / 8, 256>>>(x);                  // fp32-exact e_i/e_j
    dim3 ggrid(ROWS / 128, HD / 64);              // 64 x 4 = 256 blocks
    gemm_tf32_k<<<ggrid, 256>>>(x, W);            // tf32 tensor-core Wx
    attn_k<<<ROWS, 256>>>(adj, out);
}

// round 14
// speedup vs baseline: 1.2529x; 1.1582x over previous
#include <cuda_runtime.h>
#include <cuda_fp16.h>
#include <cstdint>

// Problem dims (fixed): B=8, N=1024, C=256, H=4, D=64
#define Bb   8
#define Nn   1024
#define Cc   256
#define Hh   4
#define Dd   64
#define HD   256               // H*D
#define ROWS (Bb * Nn)         // 8192
#define NEG_SLOPE 0.2f

// Scratch (device globals: allocation-free rule)
__device__ __half g_Wxh[ROWS * HD]; // 4 MB  (fp16 Wx — only consumer is the gather)
__device__ float  g_ei[ROWS * Hh];
__device__ float  g_ej[ROWS * Hh];
__device__ float  g_wa[8][Cc];      // W @ [a_i|a_j] per (head, i/j): v = h*2+ij

__device__ __forceinline__ uint32_t f2tf(float f) {
    uint32_t r;
    asm("cvt.rna.tf32.f32 %0, %1;" : "=r"(r) : "f"(f));
    return r;
}
__device__ __forceinline__ float f2tf_f(float f) { return __uint_as_float(f2tf(f)); }

// ---------------------------------------------------------------------------
// Kernel 0: wa[v][c] = sum_d W[c][h*64+d] * a[h, ij*64 + d],  v = h*2+ij.
// grid = 8 blocks (one per v), 256 threads (one per c). fp32-exact.
// ---------------------------------------------------------------------------
__global__ void __launch_bounds__(256) wa_k(const float* __restrict__ W,
                                            const float* __restrict__ avec) {
    __shared__ float s_a[64];
    const int v = blockIdx.x;          // 0..7
    const int h = v >> 1, ij = v & 1;
    const int tid = threadIdx.x;
    if (tid < 64) s_a[tid] = avec[h * 128 + ij * 64 + tid];
    __syncthreads();

    const float* wrow = W + (size_t)tid * HD + h * 64;
    float s = 0.0f;
#pragma unroll
    for (int d = 0; d < 64; d += 4) {
        float4 w4 = __ldg((const float4*)(wrow + d));
        s += w4.x * s_a[d] + w4.y * s_a[d + 1] + w4.z * s_a[d + 2] + w4.w * s_a[d + 3];
    }
    g_wa[v][tid] = s;
}

// ---------------------------------------------------------------------------
// Kernel 0b: e_i/e_j = x . wa  (fp32-exact). One warp per row, 8 warps/block.
// Conflict-free: lane l owns columns l, l+32, ..., l+224 (stride-32 => all 32
// banks distinct on every LDS).
// ---------------------------------------------------------------------------
__global__ void __launch_bounds__(256) eij_k(const float* __restrict__ x) {
    __shared__ float s_wa[8][Cc];      // 8 KB
    const int tid  = threadIdx.x;
    const int warp = tid >> 5;
    const int lane = tid & 31;

    // cooperative load of g_wa (2048 floats)
#pragma unroll
    for (int i = 0; i < 8; i++)
        ((float*)s_wa)[tid + i * 256] = ((const float*)g_wa)[tid + i * 256];

    const int row = blockIdx.x * 8 + warp;
    const float* xr = x + (size_t)row * Cc;
    float xv[8];
#pragma unroll
    for (int i = 0; i < 8; i++) xv[i] = __ldg(&xr[lane + 32 * i]);
    __syncthreads();

    float e[8];
#pragma unroll
    for (int v = 0; v < 8; v++) {
        float s = 0.0f;
#pragma unroll
        for (int i = 0; i < 8; i++)
            s = fmaf(xv[i], s_wa[v][lane + 32 * i], s);
        e[v] = s;
    }
#pragma unroll
    for (int off = 16; off > 0; off >>= 1)
#pragma unroll
        for (int v = 0; v < 8; v++)
            e[v] += __shfl_xor_sync(0xffffffffu, e[v], off);

    if (lane == 0) {
        *(float4*)&g_ei[row * Hh] = make_float4(e[0], e[2], e[4], e[6]);
        *(float4*)&g_ej[row * Hh] = make_float4(e[1], e[3], e[5], e[7]);
    }
}

// ---------------------------------------------------------------------------
// Kernel 1: Wx = x @ W via tf32 mma.sync (m16n8k8). 128x64 block tile,
// 8 warps (4m x 2n), warp tile 32x32 (2 mtiles x 4 ntiles). fp16 Wx store.
// (unchanged from round 11)
// ---------------------------------------------------------------------------
__global__ void __launch_bounds__(256) gemm_tf32_k(const float* __restrict__ A,
                                                   const float* __restrict__ Bm) {
    __shared__ float As[128][36];    // 32 k-cols + 4 pad (a-frag conflict-free)
    __shared__ float Bs[32][72];     // 64 n-cols + 8 pad (b-frag conflict-free)

    const int tid  = threadIdx.x;
    const int warp = tid >> 5;
    const int lane = tid & 31;
    const int qr = lane >> 2;         // 0..7
    const int qc = lane & 3;          // 0..3
    const int wm = (warp >> 1) * 32;  // warp m offset
    const int wn = (warp & 1) * 32;   // warp n offset
    const int row0 = blockIdx.x * 128;
    const int col0 = blockIdx.y * 64;

    // global load assignments
    const int a_row = tid >> 1, a_col = (tid & 1) * 16;
    const int b_row = tid >> 3, b_col = (tid & 7) * 8;
    const float* aptr = A + (size_t)(row0 + a_row) * Cc + a_col;
    const float* bptr = Bm + (size_t)b_row * HD + col0 + b_col;

    float acc[2][4][4] = {};

    // preload chunk 0
    float4 ra[4], rb[2];
#pragma unroll
    for (int i = 0; i < 4; i++) ra[i] = __ldg((const float4*)(aptr + i * 4));
    rb[0] = __ldg((const float4*)(bptr));
    rb[1] = __ldg((const float4*)(bptr + 4));

#pragma unroll
    for (int chunk = 0; chunk < 8; chunk++) {
        // stage (convert to tf32 at store time)
#pragma unroll
        for (int i = 0; i < 4; i++) {
            *(float4*)&As[a_row][a_col + i * 4] = make_float4(
                f2tf_f(ra[i].x), f2tf_f(ra[i].y), f2tf_f(ra[i].z), f2tf_f(ra[i].w));
        }
        *(float4*)&Bs[b_row][b_col] = make_float4(
            f2tf_f(rb[0].x), f2tf_f(rb[0].y), f2tf_f(rb[0].z), f2tf_f(rb[0].w));
        *(float4*)&Bs[b_row][b_col + 4] = make_float4(
            f2tf_f(rb[1].x), f2tf_f(rb[1].y), f2tf_f(rb[1].z), f2tf_f(rb[1].w));
        __syncthreads();

        if (chunk < 7) {     // prefetch next chunk
            const int k0 = (chunk + 1) * 32;
#pragma unroll
            for (int i = 0; i < 4; i++)
                ra[i] = __ldg((const float4*)(aptr + k0 + i * 4));
            rb[0] = __ldg((const float4*)(bptr + (size_t)k0 * HD));
            rb[1] = __ldg((const float4*)(bptr + (size_t)k0 * HD + 4));
        }

#pragma unroll
        for (int k8 = 0; k8 < 4; k8++) {
            const int kb = k8 * 8;
            uint32_t af[2][4], bf[4][2];
#pragma unroll
            for (int mt = 0; mt < 2; mt++) {
                const int r = wm + mt * 16 + qr;
                af[mt][0] = __float_as_uint(As[r    ][kb + qc]);
                af[mt][1] = __float_as_uint(As[r + 8][kb + qc]);
                af[mt][2] = __float_as_uint(As[r    ][kb + qc + 4]);
                af[mt][3] = __float_as_uint(As[r + 8][kb + qc + 4]);
            }
#pragma unroll
            for (int nt = 0; nt < 4; nt++) {
                const int c = wn + nt * 8 + qr;
                bf[nt][0] = __float_as_uint(Bs[kb + qc    ][c]);
                bf[nt][1] = __float_as_uint(Bs[kb + qc + 4][c]);
            }
#pragma unroll
            for (int mt = 0; mt < 2; mt++)
#pragma unroll
                for (int nt = 0; nt < 4; nt++) {
                    asm volatile(
                        "mma.sync.aligned.m16n8k8.row.col.f32.tf32.tf32.f32 "
                        "{%0,%1,%2,%3}, {%4,%5,%6,%7}, {%8,%9}, {%0,%1,%2,%3};"
                        : "+f"(acc[mt][nt][0]), "+f"(acc[mt][nt][1]),
                          "+f"(acc[mt][nt][2]), "+f"(acc[mt][nt][3])
                        : "r"(af[mt][0]), "r"(af[mt][1]), "r"(af[mt][2]), "r"(af[mt][3]),
                          "r"(bf[nt][0]), "r"(bf[nt][1]));
                }
        }
        __syncthreads();
    }

    // store Wx as fp16 directly from C fragments
#pragma unroll
    for (int mt = 0; mt < 2; mt++) {
        const int r0 = row0 + wm + mt * 16 + qr;
#pragma unroll
        for (int nt = 0; nt < 4; nt++) {
            const int c = col0 + wn + nt * 8 + qc * 2;
            __half2 h0 = __floats2half2_rn(acc[mt][nt][0], acc[mt][nt][1]);
            __half2 h1 = __floats2half2_rn(acc[mt][nt][2], acc[mt][nt][3]);
            *(__half2*)&g_Wxh[(size_t)r0 * HD + c]       = h0;
            *(__half2*)&g_Wxh[(size_t)(r0 + 8) * HD + c] = h1;
        }
    }
}

// ---------------------------------------------------------------------------
// Kernel 2: sparse masked softmax + fp16 gather (round-9 verbatim, ~37us).
// ---------------------------------------------------------------------------
__global__ void __launch_bounds__(256) attn_k(const float* __restrict__ adj,
                                              float* __restrict__ out) {
    __shared__ int   s_idx[Nn];          // compacted j*64 offsets (ordered)
    __shared__ float s_w[Nn * Hh];       // [k][h] exp-weights (float4 per k)
    __shared__ int   s_tot[8];
    __shared__ float s_rsum[8][4];
    __shared__ float s_acc[4][Hh * 64];  // [grp][pos*4] partial accumulators

    const int tid  = threadIdx.x;
    const int blk  = blockIdx.x;          // b*N + n
    const int b    = blk >> 10;
    const int n    = blk & 1023;
    const int warp = tid >> 5;
    const int lane = tid & 31;

    // ---- compaction: each thread owns 4 consecutive j ----
    const float4* arow4 = (const float4*)(adj + (size_t)blk * Nn);
    float4 v = arow4[tid];
    const int j0 = tid * 4;
    unsigned mk = 0;
    if (v.x != 0.0f || j0     == n) mk |= 1u;
    if (v.y != 0.0f || j0 + 1 == n) mk |= 2u;
    if (v.z != 0.0f || j0 + 2 == n) mk |= 4u;
    if (v.w != 0.0f || j0 + 3 == n) mk |= 8u;
    int cnt = __popc(mk);
    int scan = cnt;
#pragma unroll
    for (int off = 1; off < 32; off <<= 1) {
        int t = __shfl_up_sync(0xffffffffu, scan, off);
        if (lane >= off) scan += t;
    }
    if (lane == 31) s_tot[warp] = scan;
    __syncthreads();
    int base = 0, K = 0;
#pragma unroll
    for (int w = 0; w < 8; w++) {
        int t = s_tot[w];
        if (w < warp) base += t;
        K += t;
    }
    int pos0 = base + (scan - cnt);
    if (mk & 1u) s_idx[pos0++] = (j0    ) * 64;
    if (mk & 2u) s_idx[pos0++] = (j0 + 1) * 64;
    if (mk & 4u) s_idx[pos0++] = (j0 + 2) * 64;
    if (mk & 8u) s_idx[pos0++] = (j0 + 3) * 64;
    __syncthreads();

    // ---- fused score + exp + sum (no max-subtract: scores bounded, fp32-safe) ----
    float4 eiv = *(const float4*)&g_ei[blk * Hh];
    const float4* ej4 = (const float4*)g_ej;
    float lsum[4] = {};
    for (int k = tid; k < K; k += 256) {
        int j = s_idx[k] >> 6;
        float4 ejv = __ldg(&ej4[(b << 10) + j]);
        float s0 = eiv.x + ejv.x, s1 = eiv.y + ejv.y;
        float s2 = eiv.z + ejv.z, s3 = eiv.w + ejv.w;
        s0 = s0 > 0.0f ? s0 : NEG_SLOPE * s0;
        s1 = s1 > 0.0f ? s1 : NEG_SLOPE * s1;
        s2 = s2 > 0.0f ? s2 : NEG_SLOPE * s2;
        s3 = s3 > 0.0f ? s3 : NEG_SLOPE * s3;
        float w0 = __expf(s0), w1 = __expf(s1);
        float w2 = __expf(s2), w3 = __expf(s3);
        *(float4*)&s_w[k * Hh] = make_float4(w0, w1, w2, w3);
        lsum[0] += w0; lsum[1] += w1; lsum[2] += w2; lsum[3] += w3;
    }
#pragma unroll
    for (int off = 16; off > 0; off >>= 1)
#pragma unroll
        for (int h = 0; h < 4; h++)
            lsum[h] += __shfl_xor_sync(0xffffffffu, lsum[h], off);
    if (lane == 0)
#pragma unroll
        for (int h = 0; h < 4; h++) s_rsum[warp][h] = lsum[h];
    __syncthreads();   // orders s_w / s_idx writes before gather reads

    // ---- fp16 gather: pos owns out floats [4pos,4pos+4), grp splits k ----
    const int pos = tid & 63;
    const int grp = tid >> 6;
    const int hh  = pos >> 4;            // head of this float4
    const uint2* hw = (const uint2*)(g_Wxh + (size_t)b * (Nn * HD));
    float4 acc = make_float4(0.f, 0.f, 0.f, 0.f);
    int k = grp;
    for (; k + 12 < K; k += 16) {
        int oa = s_idx[k] + pos,     ob = s_idx[k + 4]  + pos;
        int oc = s_idx[k + 8] + pos, od = s_idx[k + 12] + pos;
        float wa = s_w[(k     ) * Hh + hh], wb = s_w[(k +  4) * Hh + hh];
        float wc = s_w[(k +  8) * Hh + hh], wd = s_w[(k + 12) * Hh + hh];
        uint2 ua = __ldg(&hw[oa]);
        uint2 ub = __ldg(&hw[ob]);
        uint2 uc = __ldg(&hw[oc]);
        uint2 ud = __ldg(&hw[od]);
        float2 a0 = __half22float2(*(__half2*)&ua.x);
        float2 a1 = __half22float2(*(__half2*)&ua.y);
        float2 b0 = __half22float2(*(__half2*)&ub.x);
        float2 b1 = __half22float2(*(__half2*)&ub.y);
        float2 c0 = __half22float2(*(__half2*)&uc.x);
        float2 c1 = __half22float2(*(__half2*)&uc.y);
        float2 d0 = __half22float2(*(__half2*)&ud.x);
        float2 d1 = __half22float2(*(__half2*)&ud.y);
        acc.x = fmaf(wa, a0.x, acc.x); acc.y = fmaf(wa, a0.y, acc.y);
        acc.z = fmaf(wa, a1.x, acc.z); acc.w = fmaf(wa, a1.y, acc.w);
        acc.x = fmaf(wb, b0.x, acc.x); acc.y = fmaf(wb, b0.y, acc.y);
        acc.z = fmaf(wb, b1.x, acc.z); acc.w = fmaf(wb, b1.y, acc.w);
        acc.x = fmaf(wc, c0.x, acc.x); acc.y = fmaf(wc, c0.y, acc.y);
        acc.z = fmaf(wc, c1.x, acc.z); acc.w = fmaf(wc, c1.y, acc.w);
        acc.x = fmaf(wd, d0.x, acc.x); acc.y = fmaf(wd, d0.y, acc.y);
        acc.z = fmaf(wd, d1.x, acc.z); acc.w = fmaf(wd, d1.y, acc.w);
    }
    for (; k < K; k += 4) {
        int o = s_idx[k] + pos;
        float w = s_w[k * Hh + hh];
        uint2 uu = __ldg(&hw[o]);
        float2 l0 = __half22float2(*(__half2*)&uu.x);
        float2 l1 = __half22float2(*(__half2*)&uu.y);
        acc.x = fmaf(w, l0.x, acc.x); acc.y = fmaf(w, l0.y, acc.y);
        acc.z = fmaf(w, l1.x, acc.z); acc.w = fmaf(w, l1.y, acc.w);
    }
    *(float4*)&s_acc[grp][pos * 4] = acc;
    __syncthreads();

    // ---- cross-group reduce + normalize + store ----
    if (tid < 64) {
        const int h = tid >> 4;
        float4 r = *(float4*)&s_acc[0][tid * 4];
#pragma unroll
        for (int g = 1; g < 4; g++) {
            float4 t = *(float4*)&s_acc[g][tid * 4];
            r.x += t.x; r.y += t.y; r.z += t.z; r.w += t.w;
        }
        float tot = 0.0f;
#pragma unroll
        for (int w = 0; w < 8; w++) tot += s_rsum[w][h];
        float inv = 1.0f / tot;
        r.x *= inv; r.y *= inv; r.z *= inv; r.w *= inv;
        *(float4*)&out[(size_t)blk * HD + tid * 4] = r;
    }
}

// ---------------------------------------------------------------------------
extern "C" void kernel_launch(void* const* d_in, const int* in_sizes, int n_in,
                              void* d_out, int out_size) {
    const float *x = nullptr, *adj = nullptr, *W = nullptr, *a = nullptr;
    for (int i = 0; i < n_in; i++) {
        switch (in_sizes[i]) {
            case Bb * Nn * Cc:  x   = (const float*)d_in[i]; break;  // 2097152
            case Bb * Nn * Nn:  adj = (const float*)d_in[i]; break;  // 8388608
            case Cc * HD:       W   = (const float*)d_in[i]; break;  // 65536
            case Hh * 2 * Dd:   a   = (const float*)d_in[i]; break;  // 512
        }
    }
    float* out = (float*)d_out;

    wa_k<<<8, 256>>>(W, a);                       // fp32-exact W@a
    eij_k<<<ROWS / 8, 256>>>(x);                  // fp32-exact e_i/e_j (conflict-free)
    dim3 ggrid(ROWS / 128, HD / 64);              // 64 x 4 = 256 blocks
    gemm_tf32_k<<<ggrid, 256>>>(x, W);            // tf32 tensor-core Wx
    attn_k<<<ROWS, 256>>>(adj, out);
}

// round 15
// speedup vs baseline: 1.2870x; 1.0273x over previous
#include <cuda_runtime.h>
#include <cuda_fp16.h>
#include <cstdint>

// Problem dims (fixed): B=8, N=1024, C=256, H=4, D=64
#define Bb   8
#define Nn   1024
#define Cc   256
#define Hh   4
#define Dd   64
#define HD   256               // H*D
#define ROWS (Bb * Nn)         // 8192
#define NEG_SLOPE 0.2f

// Scratch (device globals: allocation-free rule)
__device__ __half g_Wxh[ROWS * HD]; // 4 MB  (fp16 Wx — only consumer is the gather)
__device__ float  g_ei[ROWS * Hh];
__device__ float  g_ej[ROWS * Hh];
__device__ float  g_wa[8][Cc];      // W @ [a_i|a_j] per (head, i/j): v = h*2+ij

__device__ __forceinline__ uint32_t f2tf(float f) {
    uint32_t r;
    asm("cvt.rna.tf32.f32 %0, %1;" : "=r"(r) : "f"(f));
    return r;
}
__device__ __forceinline__ float f2tf_f(float f) { return __uint_as_float(f2tf(f)); }

// ---------------------------------------------------------------------------
// Kernel 0: wa[v][c] = sum_d W[c][h*64+d] * a[h, ij*64 + d],  v = h*2+ij.
// grid = 8 blocks (one per v), 256 threads (one per c). fp32-exact.
// ---------------------------------------------------------------------------
__global__ void __launch_bounds__(256) wa_k(const float* __restrict__ W,
                                            const float* __restrict__ avec) {
    __shared__ float s_a[64];
    const int v = blockIdx.x;          // 0..7
    const int h = v >> 1, ij = v & 1;
    const int tid = threadIdx.x;
    if (tid < 64) s_a[tid] = avec[h * 128 + ij * 64 + tid];
    __syncthreads();

    const float* wrow = W + (size_t)tid * HD + h * 64;
    float s = 0.0f;
#pragma unroll
    for (int d = 0; d < 64; d += 4) {
        float4 w4 = __ldg((const float4*)(wrow + d));
        s += w4.x * s_a[d] + w4.y * s_a[d + 1] + w4.z * s_a[d + 2] + w4.w * s_a[d + 3];
    }
    g_wa[v][tid] = s;
}

// ---------------------------------------------------------------------------
// Kernel 0b: e_i/e_j = x . wa (fp32-exact, conflict-free stride-32).
// PDL secondary of wa: loads x first, grid-syncs, then reads g_wa.
// ---------------------------------------------------------------------------
__global__ void __launch_bounds__(256) eij_k(const float* __restrict__ x) {
    __shared__ float s_wa[8][Cc];      // 8 KB
    const int tid  = threadIdx.x;
    const int warp = tid >> 5;
    const int lane = tid & 31;

    const int row = blockIdx.x * 8 + warp;
    const float* xr = x + (size_t)row * Cc;
    float xv[8];
#pragma unroll
    for (int i = 0; i < 8; i++) xv[i] = __ldg(&xr[lane + 32 * i]);

#if __CUDA_ARCH__ >= 900
    cudaGridDependencySynchronize();   // wa must be complete before g_wa read
#endif

    // cooperative load of g_wa (2048 floats)
#pragma unroll
    for (int i = 0; i < 8; i++)
        ((float*)s_wa)[tid + i * 256] = ((const float*)g_wa)[tid + i * 256];
    __syncthreads();

    float e[8];
#pragma unroll
    for (int v = 0; v < 8; v++) {
        float s = 0.0f;
#pragma unroll
        for (int i = 0; i < 8; i++)
            s = fmaf(xv[i], s_wa[v][lane + 32 * i], s);
        e[v] = s;
    }
#pragma unroll
    for (int off = 16; off > 0; off >>= 1)
#pragma unroll
        for (int v = 0; v < 8; v++)
            e[v] += __shfl_xor_sync(0xffffffffu, e[v], off);

    if (lane == 0) {
        *(float4*)&g_ei[row * Hh] = make_float4(e[0], e[2], e[4], e[6]);
        *(float4*)&g_ej[row * Hh] = make_float4(e[1], e[3], e[5], e[7]);
    }
}

// ---------------------------------------------------------------------------
// Kernel 1: Wx = x @ W via tf32 mma.sync (m16n8k8). 128x64 block tile,
// 8 warps (4m x 2n), warp tile 32x32. fp16 Wx store.
// PDL secondary of eij (data-independent — runs fully concurrent); grid-syncs
// at the END so attn's grid-sync transitively covers eij/wa.
// ---------------------------------------------------------------------------
__global__ void __launch_bounds__(256) gemm_tf32_k(const float* __restrict__ A,
                                                   const float* __restrict__ Bm) {
    __shared__ float As[128][36];    // 32 k-cols + 4 pad (a-frag conflict-free)
    __shared__ float Bs[32][72];     // 64 n-cols + 8 pad (b-frag conflict-free)

    const int tid  = threadIdx.x;
    const int warp = tid >> 5;
    const int lane = tid & 31;
    const int qr = lane >> 2;         // 0..7
    const int qc = lane & 3;          // 0..3
    const int wm = (warp >> 1) * 32;  // warp m offset
    const int wn = (warp & 1) * 32;   // warp n offset
    const int row0 = blockIdx.x * 128;
    const int col0 = blockIdx.y * 64;

    // global load assignments
    const int a_row = tid >> 1, a_col = (tid & 1) * 16;
    const int b_row = tid >> 3, b_col = (tid & 7) * 8;
    const float* aptr = A + (size_t)(row0 + a_row) * Cc + a_col;
    const float* bptr = Bm + (size_t)b_row * HD + col0 + b_col;

    float acc[2][4][4] = {};

    // preload chunk 0
    float4 ra[4], rb[2];
#pragma unroll
    for (int i = 0; i < 4; i++) ra[i] = __ldg((const float4*)(aptr + i * 4));
    rb[0] = __ldg((const float4*)(bptr));
    rb[1] = __ldg((const float4*)(bptr + 4));

#pragma unroll
    for (int chunk = 0; chunk < 8; chunk++) {
        // stage (convert to tf32 at store time)
#pragma unroll
        for (int i = 0; i < 4; i++) {
            *(float4*)&As[a_row][a_col + i * 4] = make_float4(
                f2tf_f(ra[i].x), f2tf_f(ra[i].y), f2tf_f(ra[i].z), f2tf_f(ra[i].w));
        }
        *(float4*)&Bs[b_row][b_col] = make_float4(
            f2tf_f(rb[0].x), f2tf_f(rb[0].y), f2tf_f(rb[0].z), f2tf_f(rb[0].w));
        *(float4*)&Bs[b_row][b_col + 4] = make_float4(
            f2tf_f(rb[1].x), f2tf_f(rb[1].y), f2tf_f(rb[1].z), f2tf_f(rb[1].w));
        __syncthreads();

        if (chunk < 7) {     // prefetch next chunk
            const int k0 = (chunk + 1) * 32;
#pragma unroll
            for (int i = 0; i < 4; i++)
                ra[i] = __ldg((const float4*)(aptr + k0 + i * 4));
            rb[0] = __ldg((const float4*)(bptr + (size_t)k0 * HD));
            rb[1] = __ldg((const float4*)(bptr + (size_t)k0 * HD + 4));
        }

#pragma unroll
        for (int k8 = 0; k8 < 4; k8++) {
            const int kb = k8 * 8;
            uint32_t af[2][4], bf[4][2];
#pragma unroll
            for (int mt = 0; mt < 2; mt++) {
                const int r = wm + mt * 16 + qr;
                af[mt][0] = __float_as_uint(As[r    ][kb + qc]);
                af[mt][1] = __float_as_uint(As[r + 8][kb + qc]);
                af[mt][2] = __float_as_uint(As[r    ][kb + qc + 4]);
                af[mt][3] = __float_as_uint(As[r + 8][kb + qc + 4]);
            }
#pragma unroll
            for (int nt = 0; nt < 4; nt++) {
                const int c = wn + nt * 8 + qr;
                bf[nt][0] = __float_as_uint(Bs[kb + qc    ][c]);
                bf[nt][1] = __float_as_uint(Bs[kb + qc + 4][c]);
            }
#pragma unroll
            for (int mt = 0; mt < 2; mt++)
#pragma unroll
                for (int nt = 0; nt < 4; nt++) {
                    asm volatile(
                        "mma.sync.aligned.m16n8k8.row.col.f32.tf32.tf32.f32 "
                        "{%0,%1,%2,%3}, {%4,%5,%6,%7}, {%8,%9}, {%0,%1,%2,%3};"
                        : "+f"(acc[mt][nt][0]), "+f"(acc[mt][nt][1]),
                          "+f"(acc[mt][nt][2]), "+f"(acc[mt][nt][3])
                        : "r"(af[mt][0]), "r"(af[mt][1]), "r"(af[mt][2]), "r"(af[mt][3]),
                          "r"(bf[nt][0]), "r"(bf[nt][1]));
                }
        }
        __syncthreads();
    }

    // store Wx as fp16 directly from C fragments
#pragma unroll
    for (int mt = 0; mt < 2; mt++) {
        const int r0 = row0 + wm + mt * 16 + qr;
#pragma unroll
        for (int nt = 0; nt < 4; nt++) {
            const int c = col0 + wn + nt * 8 + qc * 2;
            __half2 h0 = __floats2half2_rn(acc[mt][nt][0], acc[mt][nt][1]);
            __half2 h1 = __floats2half2_rn(acc[mt][nt][2], acc[mt][nt][3]);
            *(__half2*)&g_Wxh[(size_t)r0 * HD + c]       = h0;
            *(__half2*)&g_Wxh[(size_t)(r0 + 8) * HD + c] = h1;
        }
    }

#if __CUDA_ARCH__ >= 900
    // No data dependency on eij/wa — sync at the end only to make attn's
    // grid-sync transitively cover the whole prep chain. Near-free by now.
    cudaGridDependencySynchronize();
#endif
}

// ---------------------------------------------------------------------------
// Kernel 2: sparse masked softmax + fp16 gather. PDL secondary of gemm:
// adj read + compaction run pre-sync (independent of Wx/e), then grid-sync.
// Score pass is warp-contiguous so inactive warps skip the reduction tree.
// ---------------------------------------------------------------------------
__global__ void __launch_bounds__(256) attn_k(const float* __restrict__ adj,
                                              float* __restrict__ out) {
    __shared__ int   s_idx[Nn];          // compacted j*64 offsets (ordered)
    __shared__ float s_w[Nn * Hh];       // [k][h] exp-weights (float4 per k)
    __shared__ int   s_tot[8];
    __shared__ float s_rsum[8][4];
    __shared__ float s_acc[4][Hh * 64];  // [grp][pos*4] partial accumulators

    const int tid  = threadIdx.x;
    const int blk  = blockIdx.x;          // b*N + n
    const int b    = blk >> 10;
    const int n    = blk & 1023;
    const int warp = tid >> 5;
    const int lane = tid & 31;

    // ---- compaction: each thread owns 4 consecutive j ----
    const float4* arow4 = (const float4*)(adj + (size_t)blk * Nn);
    float4 v = arow4[tid];
    const int j0 = tid * 4;
    unsigned mk = 0;
    if (v.x != 0.0f || j0     == n) mk |= 1u;
    if (v.y != 0.0f || j0 + 1 == n) mk |= 2u;
    if (v.z != 0.0f || j0 + 2 == n) mk |= 4u;
    if (v.w != 0.0f || j0 + 3 == n) mk |= 8u;
    int cnt = __popc(mk);
    int scan = cnt;
#pragma unroll
    for (int off = 1; off < 32; off <<= 1) {
        int t = __shfl_up_sync(0xffffffffu, scan, off);
        if (lane >= off) scan += t;
    }
    if (lane == 31) s_tot[warp] = scan;
    if (tid < 32) s_rsum[tid >> 2][tid & 3] = 0.0f;   // pre-zero (warp-skip below)
    __syncthreads();
    int base = 0, K = 0;
#pragma unroll
    for (int w = 0; w < 8; w++) {
        int t = s_tot[w];
        if (w < warp) base += t;
        K += t;
    }
    int pos0 = base + (scan - cnt);
    if (mk & 1u) s_idx[pos0++] = (j0    ) * 64;
    if (mk & 2u) s_idx[pos0++] = (j0 + 1) * 64;
    if (mk & 4u) s_idx[pos0++] = (j0 + 2) * 64;
    if (mk & 8u) s_idx[pos0++] = (j0 + 3) * 64;
    __syncthreads();

#if __CUDA_ARCH__ >= 900
    cudaGridDependencySynchronize();   // g_ei/g_ej/g_Wxh producers must be done
#endif

    // ---- fused score + exp + sum, warp-contiguous k so idle warps skip ----
    float4 eiv = *(const float4*)&g_ei[blk * Hh];
    const float4* ej4 = (const float4*)g_ej;
    float lsum[4] = {};
    for (int k = warp * 32 + lane; k < K; k += 256) {
        int j = s_idx[k] >> 6;
        float4 ejv = __ldg(&ej4[(b << 10) + j]);
        float s0 = eiv.x + ejv.x, s1 = eiv.y + ejv.y;
        float s2 = eiv.z + ejv.z, s3 = eiv.w + ejv.w;
        s0 = s0 > 0.0f ? s0 : NEG_SLOPE * s0;
        s1 = s1 > 0.0f ? s1 : NEG_SLOPE * s1;
        s2 = s2 > 0.0f ? s2 : NEG_SLOPE * s2;
        s3 = s3 > 0.0f ? s3 : NEG_SLOPE * s3;
        float w0 = __expf(s0), w1 = __expf(s1);
        float w2 = __expf(s2), w3 = __expf(s3);
        *(float4*)&s_w[k * Hh] = make_float4(w0, w1, w2, w3);
        lsum[0] += w0; lsum[1] += w1; lsum[2] += w2; lsum[3] += w3;
    }
    if (warp * 32 < K) {   // uniform per warp: only warps that touched k's reduce
#pragma unroll
        for (int off = 16; off > 0; off >>= 1)
#pragma unroll
            for (int h = 0; h < 4; h++)
                lsum[h] += __shfl_xor_sync(0xffffffffu, lsum[h], off);
        if (lane == 0)
#pragma unroll
            for (int h = 0; h < 4; h++) s_rsum[warp][h] = lsum[h];
    }
    __syncthreads();   // orders s_w / s_rsum writes before gather reads

    // ---- fp16 gather: pos owns out floats [4pos,4pos+4), grp splits k ----
    const int pos = tid & 63;
    const int grp = tid >> 6;
    const int hh  = pos >> 4;            // head of this float4
    const uint2* hw = (const uint2*)(g_Wxh + (size_t)b * (Nn * HD));
    float4 acc = make_float4(0.f, 0.f, 0.f, 0.f);
    int k = grp;
    for (; k + 12 < K; k += 16) {
        int oa = s_idx[k] + pos,     ob = s_idx[k + 4]  + pos;
        int oc = s_idx[k + 8] + pos, od = s_idx[k + 12] + pos;
        float wa = s_w[(k     ) * Hh + hh], wb = s_w[(k +  4) * Hh + hh];
        float wc = s_w[(k +  8) * Hh + hh], wd = s_w[(k + 12) * Hh + hh];
        uint2 ua = __ldg(&hw[oa]);
        uint2 ub = __ldg(&hw[ob]);
        uint2 uc = __ldg(&hw[oc]);
        uint2 ud = __ldg(&hw[od]);
        float2 a0 = __half22float2(*(__half2*)&ua.x);
        float2 a1 = __half22float2(*(__half2*)&ua.y);
        float2 b0 = __half22float2(*(__half2*)&ub.x);
        float2 b1 = __half22float2(*(__half2*)&ub.y);
        float2 c0 = __half22float2(*(__half2*)&uc.x);
        float2 c1 = __half22float2(*(__half2*)&uc.y);
        float2 d0 = __half22float2(*(__half2*)&ud.x);
        float2 d1 = __half22float2(*(__half2*)&ud.y);
        acc.x = fmaf(wa, a0.x, acc.x); acc.y = fmaf(wa, a0.y, acc.y);
        acc.z = fmaf(wa, a1.x, acc.z); acc.w = fmaf(wa, a1.y, acc.w);
        acc.x = fmaf(wb, b0.x, acc.x); acc.y = fmaf(wb, b0.y, acc.y);
        acc.z = fmaf(wb, b1.x, acc.z); acc.w = fmaf(wb, b1.y, acc.w);
        acc.x = fmaf(wc, c0.x, acc.x); acc.y = fmaf(wc, c0.y, acc.y);
        acc.z = fmaf(wc, c1.x, acc.z); acc.w = fmaf(wc, c1.y, acc.w);
        acc.x = fmaf(wd, d0.x, acc.x); acc.y = fmaf(wd, d0.y, acc.y);
        acc.z = fmaf(wd, d1.x, acc.z); acc.w = fmaf(wd, d1.y, acc.w);
    }
    for (; k < K; k += 4) {
        int o = s_idx[k] + pos;
        float w = s_w[k * Hh + hh];
        uint2 uu = __ldg(&hw[o]);
        float2 l0 = __half22float2(*(__half2*)&uu.x);
        float2 l1 = __half22float2(*(__half2*)&uu.y);
        acc.x = fmaf(w, l0.x, acc.x); acc.y = fmaf(w, l0.y, acc.y);
        acc.z = fmaf(w, l1.x, acc.z); acc.w = fmaf(w, l1.y, acc.w);
    }
    *(float4*)&s_acc[grp][pos * 4] = acc;
    __syncthreads();

    // ---- cross-group reduce + normalize + store ----
    if (tid < 64) {
        const int h = tid >> 4;
        float4 r = *(float4*)&s_acc[0][tid * 4];
#pragma unroll
        for (int g = 1; g < 4; g++) {
            float4 t = *(float4*)&s_acc[g][tid * 4];
            r.x += t.x; r.y += t.y; r.z += t.z; r.w += t.w;
        }
        float tot = 0.0f;
#pragma unroll
        for (int w = 0; w < 8; w++) tot += s_rsum[w][h];
        float inv = 1.0f / tot;
        r.x *= inv; r.y *= inv; r.z *= inv; r.w *= inv;
        *(float4*)&out[(size_t)blk * HD + tid * 4] = r;
    }
}

// ---------------------------------------------------------------------------
extern "C" void kernel_launch(void* const* d_in, const int* in_sizes, int n_in,
                              void* d_out, int out_size) {
    const float *x = nullptr, *adj = nullptr, *W = nullptr, *a = nullptr;
    for (int i = 0; i < n_in; i++) {
        switch (in_sizes[i]) {
            case Bb * Nn * Cc:  x   = (const float*)d_in[i]; break;  // 2097152
            case Bb * Nn * Nn:  adj = (const float*)d_in[i]; break;  // 8388608
            case Cc * HD:       W   = (const float*)d_in[i]; break;  // 65536
            case Hh * 2 * Dd:   a   = (const float*)d_in[i]; break;  // 512
        }
    }
    float* out = (float*)d_out;

    // PDL launch helper: secondary may start while its predecessor runs;
    // each kernel grid-syncs before touching predecessor data.
    cudaLaunchAttribute pdl[1];
    pdl[0].id = cudaLaunchAttributeProgrammaticStreamSerialization;
    pdl[0].val.programmaticStreamSerializationAllowed = 1;

    wa_k<<<8, 256>>>(W, a);                        // primary (tiny)

    {   // eij: overlaps wa's tail; grid-syncs before reading g_wa
        cudaLaunchConfig_t cfg = {};
        cfg.gridDim = dim3(ROWS / 8); cfg.blockDim = dim3(256);
        cfg.stream = 0; cfg.attrs = pdl; cfg.numAttrs = 1;
        cudaLaunchKernelEx(&cfg, eij_k, x);
    }
    {   // gemm: fully independent of eij/wa data — runs concurrent with eij
        cudaLaunchConfig_t cfg = {};
        cfg.gridDim = dim3(ROWS / 128, HD / 64); cfg.blockDim = dim3(256);
        cfg.stream = 0; cfg.attrs = pdl; cfg.numAttrs = 1;
        cudaLaunchKernelEx(&cfg, gemm_tf32_k, x, W);
    }
    {   // attn: adj read + compaction overlap gemm; grid-sync before scores
        cudaLaunchConfig_t cfg = {};
        cfg.gridDim = dim3(ROWS); cfg.blockDim = dim3(256);
        cfg.stream = 0; cfg.attrs = pdl; cfg.numAttrs = 1;
        cudaLaunchKernelEx(&cfg, attn_k, (const float*)adj, out);
    }
}

// round 16
// speedup vs baseline: 1.3319x; 1.0348x over previous
#include <cuda_runtime.h>
#include <cuda_fp16.h>
#include <cstdint>

// Problem dims (fixed): B=8, N=1024, C=256, H=4, D=64
#define Bb   8
#define Nn   1024
#define Cc   256
#define Hh   4
#define Dd   64
#define HD   256               // H*D
#define ROWS (Bb * Nn)         // 8192
#define NEG_SLOPE 0.2f

// Scratch (device globals: allocation-free rule)
__device__ __half g_Wxh[ROWS * HD]; // 4 MB  (fp16 Wx — only consumer is the gather)
__device__ float  g_ei[ROWS * Hh];
__device__ float  g_ej[ROWS * Hh];
__device__ float  g_wa[8][Cc];      // W @ [a_i|a_j] per (head, i/j): v = h*2+ij

__device__ __forceinline__ uint32_t f2tf(float f) {
    uint32_t r;
    asm("cvt.rna.tf32.f32 %0, %1;" : "=r"(r) : "f"(f));
    return r;
}
__device__ __forceinline__ float f2tf_f(float f) { return __uint_as_float(f2tf(f)); }

// ---------------------------------------------------------------------------
// Kernel 0: wa[v][c] = sum_d W[c][h*64+d] * a[h, ij*64 + d],  v = h*2+ij.
// grid = 8 blocks (one per v), 256 threads (one per c). fp32-exact.
// Triggers dependents at entry so eij can launch/overlap immediately.
// ---------------------------------------------------------------------------
__global__ void __launch_bounds__(256) wa_k(const float* __restrict__ W,
                                            const float* __restrict__ avec) {
#if __CUDA_ARCH__ >= 900
    cudaTriggerProgrammaticLaunchCompletion();
#endif
    __shared__ float s_a[64];
    const int v = blockIdx.x;          // 0..7
    const int h = v >> 1, ij = v & 1;
    const int tid = threadIdx.x;
    if (tid < 64) s_a[tid] = avec[h * 128 + ij * 64 + tid];
    __syncthreads();

    const float* wrow = W + (size_t)tid * HD + h * 64;
    float s = 0.0f;
#pragma unroll
    for (int d = 0; d < 64; d += 4) {
        float4 w4 = __ldg((const float4*)(wrow + d));
        s += w4.x * s_a[d] + w4.y * s_a[d + 1] + w4.z * s_a[d + 2] + w4.w * s_a[d + 3];
    }
    g_wa[v][tid] = s;
}

// ---------------------------------------------------------------------------
// Kernel 0b: e_i/e_j = x . wa (fp32-exact, conflict-free stride-32).
// Triggers at entry (gemm is data-independent); x loads overlap wa; grid-sync
// (full wa completion + flush) before reading g_wa.
// ---------------------------------------------------------------------------
__global__ void __launch_bounds__(256) eij_k(const float* __restrict__ x) {
#if __CUDA_ARCH__ >= 900
    cudaTriggerProgrammaticLaunchCompletion();
#endif
    __shared__ float s_wa[8][Cc];      // 8 KB
    const int tid  = threadIdx.x;
    const int warp = tid >> 5;
    const int lane = tid & 31;

    const int row = blockIdx.x * 8 + warp;
    const float* xr = x + (size_t)row * Cc;
    float xv[8];
#pragma unroll
    for (int i = 0; i < 8; i++) xv[i] = __ldg(&xr[lane + 32 * i]);

#if __CUDA_ARCH__ >= 900
    cudaGridDependencySynchronize();   // wa must be complete before g_wa read
#endif

    // cooperative load of g_wa (2048 floats)
#pragma unroll
    for (int i = 0; i < 8; i++)
        ((float*)s_wa)[tid + i * 256] = ((const float*)g_wa)[tid + i * 256];
    __syncthreads();

    float e[8];
#pragma unroll
    for (int v = 0; v < 8; v++) {
        float s = 0.0f;
#pragma unroll
        for (int i = 0; i < 8; i++)
            s = fmaf(xv[i], s_wa[v][lane + 32 * i], s);
        e[v] = s;
    }
#pragma unroll
    for (int off = 16; off > 0; off >>= 1)
#pragma unroll
        for (int v = 0; v < 8; v++)
            e[v] += __shfl_xor_sync(0xffffffffu, e[v], off);

    if (lane == 0) {
        *(float4*)&g_ei[row * Hh] = make_float4(e[0], e[2], e[4], e[6]);
        *(float4*)&g_ej[row * Hh] = make_float4(e[1], e[3], e[5], e[7]);
    }
}

// ---------------------------------------------------------------------------
// Kernel 1: Wx = x @ W via tf32 mma.sync (m16n8k8). 128x64 block tile,
// 8 warps (4m x 2n), warp tile 32x32. fp16 Wx store.
// Triggers at entry so attn launches immediately (compaction overlaps MMA);
// grid-syncs at END so attn's wait transitively covers eij/wa.
// ---------------------------------------------------------------------------
__global__ void __launch_bounds__(256) gemm_tf32_k(const float* __restrict__ A,
                                                   const float* __restrict__ Bm) {
#if __CUDA_ARCH__ >= 900
    cudaTriggerProgrammaticLaunchCompletion();
#endif
    __shared__ float As[128][36];    // 32 k-cols + 4 pad (a-frag conflict-free)
    __shared__ float Bs[32][72];     // 64 n-cols + 8 pad (b-frag conflict-free)

    const int tid  = threadIdx.x;
    const int warp = tid >> 5;
    const int lane = tid & 31;
    const int qr = lane >> 2;         // 0..7
    const int qc = lane & 3;          // 0..3
    const int wm = (warp >> 1) * 32;  // warp m offset
    const int wn = (warp & 1) * 32;   // warp n offset
    const int row0 = blockIdx.x * 128;
    const int col0 = blockIdx.y * 64;

    // global load assignments
    const int a_row = tid >> 1, a_col = (tid & 1) * 16;
    const int b_row = tid >> 3, b_col = (tid & 7) * 8;
    const float* aptr = A + (size_t)(row0 + a_row) * Cc + a_col;
    const float* bptr = Bm + (size_t)b_row * HD + col0 + b_col;

    float acc[2][4][4] = {};

    // preload chunk 0
    float4 ra[4], rb[2];
#pragma unroll
    for (int i = 0; i < 4; i++) ra[i] = __ldg((const float4*)(aptr + i * 4));
    rb[0] = __ldg((const float4*)(bptr));
    rb[1] = __ldg((const float4*)(bptr + 4));

#pragma unroll
    for (int chunk = 0; chunk < 8; chunk++) {
        // stage (convert to tf32 at store time)
#pragma unroll
        for (int i = 0; i < 4; i++) {
            *(float4*)&As[a_row][a_col + i * 4] = make_float4(
                f2tf_f(ra[i].x), f2tf_f(ra[i].y), f2tf_f(ra[i].z), f2tf_f(ra[i].w));
        }
        *(float4*)&Bs[b_row][b_col] = make_float4(
            f2tf_f(rb[0].x), f2tf_f(rb[0].y), f2tf_f(rb[0].z), f2tf_f(rb[0].w));
        *(float4*)&Bs[b_row][b_col + 4] = make_float4(
            f2tf_f(rb[1].x), f2tf_f(rb[1].y), f2tf_f(rb[1].z), f2tf_f(rb[1].w));
        __syncthreads();

        if (chunk < 7) {     // prefetch next chunk
            const int k0 = (chunk + 1) * 32;
#pragma unroll
            for (int i = 0; i < 4; i++)
                ra[i] = __ldg((const float4*)(aptr + k0 + i * 4));
            rb[0] = __ldg((const float4*)(bptr + (size_t)k0 * HD));
            rb[1] = __ldg((const float4*)(bptr + (size_t)k0 * HD + 4));
        }

#pragma unroll
        for (int k8 = 0; k8 < 4; k8++) {
            const int kb = k8 * 8;
            uint32_t af[2][4], bf[4][2];
#pragma unroll
            for (int mt = 0; mt < 2; mt++) {
                const int r = wm + mt * 16 + qr;
                af[mt][0] = __float_as_uint(As[r    ][kb + qc]);
                af[mt][1] = __float_as_uint(As[r + 8][kb + qc]);
                af[mt][2] = __float_as_uint(As[r    ][kb + qc + 4]);
                af[mt][3] = __float_as_uint(As[r + 8][kb + qc + 4]);
            }
#pragma unroll
            for (int nt = 0; nt < 4; nt++) {
                const int c = wn + nt * 8 + qr;
                bf[nt][0] = __float_as_uint(Bs[kb + qc    ][c]);
                bf[nt][1] = __float_as_uint(Bs[kb + qc + 4][c]);
            }
#pragma unroll
            for (int mt = 0; mt < 2; mt++)
#pragma unroll
                for (int nt = 0; nt < 4; nt++) {
                    asm volatile(
                        "mma.sync.aligned.m16n8k8.row.col.f32.tf32.tf32.f32 "
                        "{%0,%1,%2,%3}, {%4,%5,%6,%7}, {%8,%9}, {%0,%1,%2,%3};"
                        : "+f"(acc[mt][nt][0]), "+f"(acc[mt][nt][1]),
                          "+f"(acc[mt][nt][2]), "+f"(acc[mt][nt][3])
                        : "r"(af[mt][0]), "r"(af[mt][1]), "r"(af[mt][2]), "r"(af[mt][3]),
                          "r"(bf[nt][0]), "r"(bf[nt][1]));
                }
        }
        __syncthreads();
    }

    // store Wx as fp16 directly from C fragments
#pragma unroll
    for (int mt = 0; mt < 2; mt++) {
        const int r0 = row0 + wm + mt * 16 + qr;
#pragma unroll
        for (int nt = 0; nt < 4; nt++) {
            const int c = col0 + wn + nt * 8 + qc * 2;
            __half2 h0 = __floats2half2_rn(acc[mt][nt][0], acc[mt][nt][1]);
            __half2 h1 = __floats2half2_rn(acc[mt][nt][2], acc[mt][nt][3]);
            *(__half2*)&g_Wxh[(size_t)r0 * HD + c]       = h0;
            *(__half2*)&g_Wxh[(size_t)(r0 + 8) * HD + c] = h1;
        }
    }

#if __CUDA_ARCH__ >= 900
    // No data dependency on eij/wa — sync at the end only to make attn's
    // wait transitively cover the whole prep chain.
    cudaGridDependencySynchronize();
#endif
}

// ---------------------------------------------------------------------------
// Kernel 2: sparse masked softmax + fp16 gather. Launches during gemm (PDL):
// adj read + compaction run pre-wait (independent of Wx/e), then grid-sync.
// ---------------------------------------------------------------------------
__global__ void __launch_bounds__(256) attn_k(const float* __restrict__ adj,
                                              float* __restrict__ out) {
    __shared__ int   s_idx[Nn];          // compacted j*64 offsets (ordered)
    __shared__ float s_w[Nn * Hh];       // [k][h] exp-weights (float4 per k)
    __shared__ int   s_tot[8];
    __shared__ float s_rsum[8][4];
    __shared__ float s_acc[4][Hh * 64];  // [grp][pos*4] partial accumulators

    const int tid  = threadIdx.x;
    const int blk  = blockIdx.x;          // b*N + n
    const int b    = blk >> 10;
    const int n    = blk & 1023;
    const int warp = tid >> 5;
    const int lane = tid & 31;

    // ---- compaction: each thread owns 4 consecutive j ----
    const float4* arow4 = (const float4*)(adj + (size_t)blk * Nn);
    float4 v = arow4[tid];
    const int j0 = tid * 4;
    unsigned mk = 0;
    if (v.x != 0.0f || j0     == n) mk |= 1u;
    if (v.y != 0.0f || j0 + 1 == n) mk |= 2u;
    if (v.z != 0.0f || j0 + 2 == n) mk |= 4u;
    if (v.w != 0.0f || j0 + 3 == n) mk |= 8u;
    int cnt = __popc(mk);
    int scan = cnt;
#pragma unroll
    for (int off = 1; off < 32; off <<= 1) {
        int t = __shfl_up_sync(0xffffffffu, scan, off);
        if (lane >= off) scan += t;
    }
    if (lane == 31) s_tot[warp] = scan;
    if (tid < 32) s_rsum[tid >> 2][tid & 3] = 0.0f;   // pre-zero (warp-skip below)
    __syncthreads();
    int base = 0, K = 0;
#pragma unroll
    for (int w = 0; w < 8; w++) {
        int t = s_tot[w];
        if (w < warp) base += t;
        K += t;
    }
    int pos0 = base + (scan - cnt);
    if (mk & 1u) s_idx[pos0++] = (j0    ) * 64;
    if (mk & 2u) s_idx[pos0++] = (j0 + 1) * 64;
    if (mk & 4u) s_idx[pos0++] = (j0 + 2) * 64;
    if (mk & 8u) s_idx[pos0++] = (j0 + 3) * 64;
    __syncthreads();

#if __CUDA_ARCH__ >= 900
    cudaGridDependencySynchronize();   // g_ei/g_ej/g_Wxh producers must be done
#endif

    // ---- fused score + exp + sum, warp-contiguous k so idle warps skip ----
    float4 eiv = *(const float4*)&g_ei[blk * Hh];
    const float4* ej4 = (const float4*)g_ej;
    float lsum[4] = {};
    for (int k = warp * 32 + lane; k < K; k += 256) {
        int j = s_idx[k] >> 6;
        float4 ejv = __ldg(&ej4[(b << 10) + j]);
        float s0 = eiv.x + ejv.x, s1 = eiv.y + ejv.y;
        float s2 = eiv.z + ejv.z, s3 = eiv.w + ejv.w;
        s0 = s0 > 0.0f ? s0 : NEG_SLOPE * s0;
        s1 = s1 > 0.0f ? s1 : NEG_SLOPE * s1;
        s2 = s2 > 0.0f ? s2 : NEG_SLOPE * s2;
        s3 = s3 > 0.0f ? s3 : NEG_SLOPE * s3;
        float w0 = __expf(s0), w1 = __expf(s1);
        float w2 = __expf(s2), w3 = __expf(s3);
        *(float4*)&s_w[k * Hh] = make_float4(w0, w1, w2, w3);
        lsum[0] += w0; lsum[1] += w1; lsum[2] += w2; lsum[3] += w3;
    }
    if (warp * 32 < K) {   // uniform per warp: only warps that touched k's reduce
#pragma unroll
        for (int off = 16; off > 0; off >>= 1)
#pragma unroll
            for (int h = 0; h < 4; h++)
                lsum[h] += __shfl_xor_sync(0xffffffffu, lsum[h], off);
        if (lane == 0)
#pragma unroll
            for (int h = 0; h < 4; h++) s_rsum[warp][h] = lsum[h];
    }
    __syncthreads();   // orders s_w / s_rsum writes before gather reads

    // ---- fp16 gather: pos owns out floats [4pos,4pos+4), grp splits k ----
    const int pos = tid & 63;
    const int grp = tid >> 6;
    const int hh  = pos >> 4;            // head of this float4
    const uint2* hw = (const uint2*)(g_Wxh + (size_t)b * (Nn * HD));
    float4 acc = make_float4(0.f, 0.f, 0.f, 0.f);
    int k = grp;
    for (; k + 12 < K; k += 16) {
        int oa = s_idx[k] + pos,     ob = s_idx[k + 4]  + pos;
        int oc = s_idx[k + 8] + pos, od = s_idx[k + 12] + pos;
        float wa = s_w[(k     ) * Hh + hh], wb = s_w[(k +  4) * Hh + hh];
        float wc = s_w[(k +  8) * Hh + hh], wd = s_w[(k + 12) * Hh + hh];
        uint2 ua = __ldg(&hw[oa]);
        uint2 ub = __ldg(&hw[ob]);
        uint2 uc = __ldg(&hw[oc]);
        uint2 ud = __ldg(&hw[od]);
        float2 a0 = __half22float2(*(__half2*)&ua.x);
        float2 a1 = __half22float2(*(__half2*)&ua.y);
        float2 b0 = __half22float2(*(__half2*)&ub.x);
        float2 b1 = __half22float2(*(__half2*)&ub.y);
        float2 c0 = __half22float2(*(__half2*)&uc.x);
        float2 c1 = __half22float2(*(__half2*)&uc.y);
        float2 d0 = __half22float2(*(__half2*)&ud.x);
        float2 d1 = __half22float2(*(__half2*)&ud.y);
        acc.x = fmaf(wa, a0.x, acc.x); acc.y = fmaf(wa, a0.y, acc.y);
        acc.z = fmaf(wa, a1.x, acc.z); acc.w = fmaf(wa, a1.y, acc.w);
        acc.x = fmaf(wb, b0.x, acc.x); acc.y = fmaf(wb, b0.y, acc.y);
        acc.z = fmaf(wb, b1.x, acc.z); acc.w = fmaf(wb, b1.y, acc.w);
        acc.x = fmaf(wc, c0.x, acc.x); acc.y = fmaf(wc, c0.y, acc.y);
        acc.z = fmaf(wc, c1.x, acc.z); acc.w = fmaf(wc, c1.y, acc.w);
        acc.x = fmaf(wd, d0.x, acc.x); acc.y = fmaf(wd, d0.y, acc.y);
        acc.z = fmaf(wd, d1.x, acc.z); acc.w = fmaf(wd, d1.y, acc.w);
    }
    for (; k < K; k += 4) {
        int o = s_idx[k] + pos;
        float w = s_w[k * Hh + hh];
        uint2 uu = __ldg(&hw[o]);
        float2 l0 = __half22float2(*(__half2*)&uu.x);
        float2 l1 = __half22float2(*(__half2*)&uu.y);
        acc.x = fmaf(w, l0.x, acc.x); acc.y = fmaf(w, l0.y, acc.y);
        acc.z = fmaf(w, l1.x, acc.z); acc.w = fmaf(w, l1.y, acc.w);
    }
    *(float4*)&s_acc[grp][pos * 4] = acc;
    __syncthreads();

    // ---- cross-group reduce + normalize + store ----
    if (tid < 64) {
        const int h = tid >> 4;
        float4 r = *(float4*)&s_acc[0][tid * 4];
#pragma unroll
        for (int g = 1; g < 4; g++) {
            float4 t = *(float4*)&s_acc[g][tid * 4];
            r.x += t.x; r.y += t.y; r.z += t.z; r.w += t.w;
        }
        float tot = 0.0f;
#pragma unroll
        for (int w = 0; w < 8; w++) tot += s_rsum[w][h];
        float inv = 1.0f / tot;
        r.x *= inv; r.y *= inv; r.z *= inv; r.w *= inv;
        *(float4*)&out[(size_t)blk * HD + tid * 4] = r;
    }
}

// ---------------------------------------------------------------------------
extern "C" void kernel_launch(void* const* d_in, const int* in_sizes, int n_in,
                              void* d_out, int out_size) {
    const float *x = nullptr, *adj = nullptr, *W = nullptr, *a = nullptr;
    for (int i = 0; i < n_in; i++) {
        switch (in_sizes[i]) {
            case Bb * Nn * Cc:  x   = (const float*)d_in[i]; break;  // 2097152
            case Bb * Nn * Nn:  adj = (const float*)d_in[i]; break;  // 8388608
            case Cc * HD:       W   = (const float*)d_in[i]; break;  // 65536
            case Hh * 2 * Dd:   a   = (const float*)d_in[i]; break;  // 512
        }
    }
    float* out = (float*)d_out;

    // PDL: primaries trigger at entry; secondaries grid-sync before use.
    cudaLaunchAttribute pdl[1];
    pdl[0].id = cudaLaunchAttributeProgrammaticStreamSerialization;
    pdl[0].val.programmaticStreamSerializationAllowed = 1;

    wa_k<<<8, 256>>>(W, a);                        // head of chain

    {   // eij: launches during wa; x loads overlap; waits before g_wa read
        cudaLaunchConfig_t cfg = {};
        cfg.gridDim = dim3(ROWS / 8); cfg.blockDim = dim3(256);
        cfg.stream = 0; cfg.attrs = pdl; cfg.numAttrs = 1;
        cudaLaunchKernelEx(&cfg, eij_k, x);
    }
    {   // gemm: launches during eij (data-independent), fully concurrent
        cudaLaunchConfig_t cfg = {};
        cfg.gridDim = dim3(ROWS / 128, HD / 64); cfg.blockDim = dim3(256);
        cfg.stream = 0; cfg.attrs = pdl; cfg.numAttrs = 1;
        cudaLaunchKernelEx(&cfg, gemm_tf32_k, x, W);
    }
    {   // attn: launches during gemm; compaction overlaps; waits before scores
        cudaLaunchConfig_t cfg = {};
        cfg.gridDim = dim3(ROWS); cfg.blockDim = dim3(256);
        cfg.stream = 0; cfg.attrs = pdl; cfg.numAttrs = 1;
        cudaLaunchKernelEx(&cfg, attn_k, (const float*)adj, out);
    }
}